// round 1
// baseline (speedup 1.0000x reference)
#include <cuda_runtime.h>
#include <math.h>

#define KSZ 7
#define PAD 3

// Problem constants
#define B_  8
#define T_  16
#define C_  256
#define HW_ 784
#define HW4_ 196          // HW_/4 (float4)

// Scratch (no allocations allowed)
__device__ float d_pooled[B_ * C_ * T_];      // [b][c][t]
__device__ float d_Kern[B_ * C_ * KSZ];       // [b][c][k]
__device__ float d_Local[B_ * C_ * T_];       // [b][c][t]

// ---------------------------------------------------------------------------
// Kernel 1: spatial mean pool. One warp per (b,t,c) row (784 contiguous f32).
// ---------------------------------------------------------------------------
__global__ void pool_kernel(const float* __restrict__ x) {
    const int warp = threadIdx.x >> 5;
    const int lane = threadIdx.x & 31;
    const int row  = blockIdx.x * 8 + warp;       // row = (b*T + t)*C + c, 32768 rows
    const float4* xr = reinterpret_cast<const float4*>(x) + (size_t)row * HW4_;

    float s = 0.f;
    #pragma unroll
    for (int i = lane; i < HW4_; i += 32) {
        float4 v = xr[i];
        s += (v.x + v.y) + (v.z + v.w);
    }
    #pragma unroll
    for (int o = 16; o > 0; o >>= 1) s += __shfl_xor_sync(0xffffffffu, s, o);

    if (lane == 0) {
        int c  = row & (C_ - 1);
        int bt = row >> 8;          // b*T + t
        int t  = bt & (T_ - 1);
        int b  = bt >> 4;
        d_pooled[(b * C_ + c) * T_ + t] = s * (1.0f / (float)HW_);
    }
}

// ---------------------------------------------------------------------------
// Kernel 2: coefficients. One block per batch b, 256 threads.
//   G branch (thread = c): g = tanh(pooled @ W1^T); s = g @ W2^T; K = softmax(s)
//   L branch: y[o,t] = tanh(conv1d(pooled, Wl1, pad=3)); local = sigmoid(Wl2 @ y)
// ---------------------------------------------------------------------------
__global__ void coeff_kernel(const float* __restrict__ W1,   // [32][16]
                             const float* __restrict__ W2,   // [7][32]
                             const float* __restrict__ Wl1,  // [64][256][7]
                             const float* __restrict__ Wl2)  // [256][64]
{
    __shared__ float ps[C_][T_ + 2 * PAD];   // pooled, zero-padded in t
    __shared__ float w1s[32 * 16];
    __shared__ float w2s[7 * 32];
    __shared__ float ys[64][T_];

    const int b   = blockIdx.x;
    const int tid = threadIdx.x;

    // zero pad region + load pooled
    for (int i = tid; i < C_ * (T_ + 2 * PAD); i += 256)
        (&ps[0][0])[i] = 0.f;
    __syncthreads();
    for (int i = tid; i < C_ * T_; i += 256) {
        int c = i >> 4, t = i & 15;
        ps[c][t + PAD] = d_pooled[b * (C_ * T_) + i];
    }
    for (int i = tid; i < 512; i += 256) w1s[i] = W1[i];
    if (tid < 224) w2s[tid] = W2[tid];
    __syncthreads();

    // ---- G branch: one thread per channel c ----
    {
        const int c = tid;
        float p[T_];
        #pragma unroll
        for (int t = 0; t < T_; t++) p[t] = ps[c][t + PAD];

        float s[KSZ];
        #pragma unroll
        for (int k = 0; k < KSZ; k++) s[k] = 0.f;

        for (int u = 0; u < 32; u++) {
            float acc = 0.f;
            #pragma unroll
            for (int t = 0; t < T_; t++) acc += p[t] * w1s[u * 16 + t];
            float g = tanhf(acc);
            #pragma unroll
            for (int k = 0; k < KSZ; k++) s[k] += g * w2s[k * 32 + u];
        }
        float m = s[0];
        #pragma unroll
        for (int k = 1; k < KSZ; k++) m = fmaxf(m, s[k]);
        float e[KSZ], sum = 0.f;
        #pragma unroll
        for (int k = 0; k < KSZ; k++) { e[k] = expf(s[k] - m); sum += e[k]; }
        float inv = 1.0f / sum;
        #pragma unroll
        for (int k = 0; k < KSZ; k++)
            d_Kern[(b * C_ + c) * KSZ + k] = e[k] * inv;
    }

    // ---- L branch stage 1: y[o][t], 1024 values over 256 threads ----
    for (int idx = tid; idx < 64 * T_; idx += 256) {
        int o = idx >> 4, t = idx & 15;
        const float* w = Wl1 + o * (C_ * KSZ);
        float acc = 0.f;
        for (int i = 0; i < C_; i++) {
            #pragma unroll
            for (int k = 0; k < KSZ; k++)
                acc += w[i * KSZ + k] * ps[i][t + k];
        }
        ys[o][t] = tanhf(acc);
    }
    __syncthreads();

    // ---- L branch stage 2: local[c][t] = sigmoid(Wl2[c,:] @ ys[:,t]) ----
    {
        const int c = tid;
        float wr[64];
        #pragma unroll
        for (int o = 0; o < 64; o++) wr[o] = Wl2[c * 64 + o];
        #pragma unroll
        for (int t = 0; t < T_; t++) {
            float acc = 0.f;
            #pragma unroll
            for (int o = 0; o < 64; o++) acc += wr[o] * ys[o][t];
            d_Local[(b * C_ + c) * T_ + t] = 1.0f / (1.0f + expf(-acc));
        }
    }
}

// ---------------------------------------------------------------------------
// Kernel 3: main. One block per (b,c); 196 threads x float4 cover 784 spatial
// positions. Each thread loads all 16 temporal slices (read x once), applies
// the sigmoid gate, then the banded 7-tap per-(b,c) temporal conv.
// Layout of x and out are identical ([b,t,c,h,w]).
// ---------------------------------------------------------------------------
__global__ void tam_main_kernel(const float* __restrict__ x,
                                float* __restrict__ out)
{
    const int bc = blockIdx.x;             // b*C + c
    const int b  = bc >> 8;
    const int c  = bc & (C_ - 1);
    const int tid = threadIdx.x;           // 0..195

    // broadcast coefficient loads (uniform address per block)
    float kr[KSZ];
    #pragma unroll
    for (int k = 0; k < KSZ; k++) kr[k] = d_Kern[bc * KSZ + k];
    float lr[T_];
    #pragma unroll
    for (int t = 0; t < T_; t++) lr[t] = d_Local[bc * T_ + t];

    const size_t base = (size_t)(b * T_ * C_ + c) * HW4_ + tid;  // t=0 slice
    const int tstride = C_ * HW4_;                               // float4 stride per t
    const float4* xp = reinterpret_cast<const float4*>(x) + base;
    float4*       op = reinterpret_cast<float4*>(out) + base;

    float4 g[T_];
    #pragma unroll
    for (int t = 0; t < T_; t++) {
        float4 v = xp[t * tstride];
        float l = lr[t];
        g[t].x = v.x * l; g[t].y = v.y * l; g[t].z = v.z * l; g[t].w = v.w * l;
    }

    #pragma unroll
    for (int t = 0; t < T_; t++) {
        float4 a; a.x = a.y = a.z = a.w = 0.f;
        #pragma unroll
        for (int k = 0; k < KSZ; k++) {
            int ts = t + k - PAD;
            if (ts >= 0 && ts < T_) {           // constant-folded after unroll
                float kk = kr[k];
                a.x += kk * g[ts].x;
                a.y += kk * g[ts].y;
                a.z += kk * g[ts].z;
                a.w += kk * g[ts].w;
            }
        }
        op[t * tstride] = a;
    }
}

// ---------------------------------------------------------------------------
extern "C" void kernel_launch(void* const* d_in, const int* in_sizes, int n_in,
                              void* d_out, int out_size) {
    const float* x   = (const float*)d_in[0];
    const float* W1  = (const float*)d_in[1];
    const float* W2  = (const float*)d_in[2];
    const float* Wl1 = (const float*)d_in[3];
    const float* Wl2 = (const float*)d_in[4];
    float* out = (float*)d_out;

    pool_kernel<<<(B_ * T_ * C_) / 8, 256>>>(x);
    coeff_kernel<<<B_, 256>>>(W1, W2, Wl1, Wl2);
    tam_main_kernel<<<B_ * C_, HW4_>>>(x, out);
}

// round 2
// speedup vs baseline: 2.0872x; 2.0872x over previous
#include <cuda_runtime.h>
#include <math.h>

#define KSZ 7
#define PAD 3

#define B_  8
#define T_  16
#define C_  256
#define HW_ 784
#define HW4_ 196          // HW_/4 (float4)
#define NBC (B_ * C_)     // 2048
#define PSROW (T_ + 2 * PAD + 1)   // 23 (padded row, fewer bank conflicts)

// Scratch (no allocations allowed)
__device__ float d_pooled[B_ * C_ * T_];      // [b][c][t]
__device__ float d_Kern[B_ * C_ * KSZ];       // [b][c][k]
__device__ float d_Local[B_ * C_ * T_];       // [b][c][t]
__device__ float d_Y[B_ * 64 * T_];           // [b][o][t]

// ---------------------------------------------------------------------------
// Kernel 1: spatial mean pool. One warp per (b,t,c) row (784 contiguous f32).
// ---------------------------------------------------------------------------
__global__ void pool_kernel(const float* __restrict__ x) {
    const int warp = threadIdx.x >> 5;
    const int lane = threadIdx.x & 31;
    const int row  = blockIdx.x * 8 + warp;       // (b*T + t)*C + c, 32768 rows
    const float4* xr = reinterpret_cast<const float4*>(x) + (size_t)row * HW4_;

    float s = 0.f;
    #pragma unroll 7
    for (int i = lane; i < HW4_; i += 32) {
        float4 v = xr[i];
        s += (v.x + v.y) + (v.z + v.w);
    }
    #pragma unroll
    for (int o = 16; o > 0; o >>= 1) s += __shfl_xor_sync(0xffffffffu, s, o);

    if (lane == 0) {
        int c  = row & (C_ - 1);
        int bt = row >> 8;
        int t  = bt & (T_ - 1);
        int b  = bt >> 4;
        d_pooled[(b * C_ + c) * T_ + t] = s * (1.0f / (float)HW_);
    }
}

// ---------------------------------------------------------------------------
// Kernel 2a: G branch. Grid = B_, 256 threads (thread = channel c).
//   g = tanh(pooled @ W1^T); s = g @ W2^T; K = softmax(s)
// ---------------------------------------------------------------------------
__global__ void gbranch_kernel(const float* __restrict__ W1,   // [32][16]
                               const float* __restrict__ W2)   // [7][32]
{
    __shared__ float w1s[32 * 16];
    __shared__ float w2s[7 * 32];
    const int b = blockIdx.x;
    const int c = threadIdx.x;

    for (int i = c; i < 512; i += 256) w1s[i] = W1[i];
    if (c < 224) w2s[c] = W2[c];
    __syncthreads();

    float p[T_];
    const float4* pp = reinterpret_cast<const float4*>(d_pooled + (b * C_ + c) * T_);
    #pragma unroll
    for (int q = 0; q < 4; q++) {
        float4 v = pp[q];
        p[q * 4 + 0] = v.x; p[q * 4 + 1] = v.y; p[q * 4 + 2] = v.z; p[q * 4 + 3] = v.w;
    }

    float s[KSZ];
    #pragma unroll
    for (int k = 0; k < KSZ; k++) s[k] = 0.f;

    for (int u = 0; u < 32; u++) {
        float acc = 0.f;
        #pragma unroll
        for (int t = 0; t < T_; t++) acc += p[t] * w1s[u * 16 + t];
        float g = tanhf(acc);
        #pragma unroll
        for (int k = 0; k < KSZ; k++) s[k] += g * w2s[k * 32 + u];
    }
    float m = s[0];
    #pragma unroll
    for (int k = 1; k < KSZ; k++) m = fmaxf(m, s[k]);
    float e[KSZ], sum = 0.f;
    #pragma unroll
    for (int k = 0; k < KSZ; k++) { e[k] = expf(s[k] - m); sum += e[k]; }
    float inv = 1.0f / sum;
    #pragma unroll
    for (int k = 0; k < KSZ; k++)
        d_Kern[(b * C_ + c) * KSZ + k] = e[k] * inv;
}

// ---------------------------------------------------------------------------
// Kernel 2b: L-branch conv1d stage. Grid = (64 o, 8 b), 128 threads.
//   y[b,o,t] = tanh( sum_i sum_k Wl1[o,i,k] * pooled_pad[b,i,t+k] )
//   Coalesced Wl1 reads; each thread owns 2 input channels; warp+smem reduce.
// ---------------------------------------------------------------------------
__global__ void lconv_kernel(const float* __restrict__ Wl1)    // [64][256][7]
{
    __shared__ float ps[C_ * PSROW];      // padded pooled, 23-float rows
    __shared__ float red[4][T_];

    const int o = blockIdx.x;
    const int b = blockIdx.y;
    const int tid  = threadIdx.x;         // 0..127
    const int lane = tid & 31;
    const int wrp  = tid >> 5;

    for (int i = tid; i < C_ * PSROW; i += 128) ps[i] = 0.f;
    __syncthreads();
    const float4* pp = reinterpret_cast<const float4*>(d_pooled + b * C_ * T_);
    for (int i = tid; i < C_ * T_ / 4; i += 128) {
        float4 v = pp[i];
        int e0 = i * 4;
        int c = e0 >> 4, t = e0 & 15;
        float* r = &ps[c * PSROW + PAD + t];
        r[0] = v.x; r[1] = v.y; r[2] = v.z; r[3] = v.w;
    }
    __syncthreads();

    float acc[T_];
    #pragma unroll
    for (int t = 0; t < T_; t++) acc[t] = 0.f;

    const float* w = Wl1 + o * (C_ * KSZ);
    #pragma unroll
    for (int ii = 0; ii < 2; ii++) {
        const int i = tid * 2 + ii;
        float wk[KSZ];
        #pragma unroll
        for (int k = 0; k < KSZ; k++) wk[k] = w[i * KSZ + k];
        float pv[T_ + 2 * PAD];
        #pragma unroll
        for (int j = 0; j < T_ + 2 * PAD; j++) pv[j] = ps[i * PSROW + j];
        #pragma unroll
        for (int t = 0; t < T_; t++) {
            #pragma unroll
            for (int k = 0; k < KSZ; k++)
                acc[t] += wk[k] * pv[t + k];
        }
    }

    #pragma unroll
    for (int off = 16; off > 0; off >>= 1) {
        #pragma unroll
        for (int t = 0; t < T_; t++)
            acc[t] += __shfl_xor_sync(0xffffffffu, acc[t], off);
    }
    if (lane == 0) {
        #pragma unroll
        for (int t = 0; t < T_; t++) red[wrp][t] = acc[t];
    }
    __syncthreads();
    if (tid < T_) {
        float s = red[0][tid] + red[1][tid] + red[2][tid] + red[3][tid];
        d_Y[(b * 64 + o) * T_ + tid] = tanhf(s);
    }
}

// ---------------------------------------------------------------------------
// Kernel 2c: local gate. Grid = B_, 256 threads (thread = c).
//   local[b,c,t] = sigmoid( Wl2[c,:] @ y[b,:,t] )
// ---------------------------------------------------------------------------
__global__ void local_kernel(const float* __restrict__ Wl2)    // [256][64]
{
    __shared__ float ys[64 * T_];
    const int b = blockIdx.x;
    const int c = threadIdx.x;

    for (int i = c; i < 64 * T_; i += 256) ys[i] = d_Y[b * 64 * T_ + i];
    __syncthreads();

    float wr[64];
    #pragma unroll
    for (int o = 0; o < 64; o++) wr[o] = Wl2[c * 64 + o];

    #pragma unroll
    for (int t = 0; t < T_; t++) {
        float acc = 0.f;
        #pragma unroll
        for (int o = 0; o < 64; o++) acc += wr[o] * ys[o * T_ + t];
        d_Local[(b * C_ + c) * T_ + t] = 1.0f / (1.0f + expf(-acc));
    }
}

// ---------------------------------------------------------------------------
// Kernel 3: main. Flat 256-thread blocks; one float4 lane per thread covering
// all 16 temporal slices (read x once, write once).
// ---------------------------------------------------------------------------
__global__ void __launch_bounds__(256)
tam_main_kernel(const float* __restrict__ x, float* __restrict__ out)
{
    const int g  = blockIdx.x * 256 + threadIdx.x;     // < 2048*196
    const int bc = g / HW4_;
    const int sp = g - bc * HW4_;
    const int b  = bc >> 8;
    const int c  = bc & (C_ - 1);

    float kr[KSZ];
    #pragma unroll
    for (int k = 0; k < KSZ; k++) kr[k] = d_Kern[bc * KSZ + k];
    float lr[T_];
    #pragma unroll
    for (int t = 0; t < T_; t++) lr[t] = d_Local[bc * T_ + t];

    const size_t base = (size_t)(b * T_ * C_ + c) * HW4_ + sp;   // t=0 slice
    const int tstride = C_ * HW4_;
    const float4* xp = reinterpret_cast<const float4*>(x) + base;
    float4*       op = reinterpret_cast<float4*>(out) + base;

    float4 gt[T_];
    #pragma unroll
    for (int t = 0; t < T_; t++) {
        float4 v = xp[t * tstride];
        float l = lr[t];
        gt[t].x = v.x * l; gt[t].y = v.y * l; gt[t].z = v.z * l; gt[t].w = v.w * l;
    }

    #pragma unroll
    for (int t = 0; t < T_; t++) {
        float4 a; a.x = a.y = a.z = a.w = 0.f;
        #pragma unroll
        for (int k = 0; k < KSZ; k++) {
            int ts = t + k - PAD;
            if (ts >= 0 && ts < T_) {             // constant-folded
                float kk = kr[k];
                a.x += kk * gt[ts].x;
                a.y += kk * gt[ts].y;
                a.z += kk * gt[ts].z;
                a.w += kk * gt[ts].w;
            }
        }
        op[t * tstride] = a;
    }
}

// ---------------------------------------------------------------------------
extern "C" void kernel_launch(void* const* d_in, const int* in_sizes, int n_in,
                              void* d_out, int out_size) {
    const float* x   = (const float*)d_in[0];
    const float* W1  = (const float*)d_in[1];
    const float* W2  = (const float*)d_in[2];
    const float* Wl1 = (const float*)d_in[3];
    const float* Wl2 = (const float*)d_in[4];
    float* out = (float*)d_out;

    pool_kernel<<<(B_ * T_ * C_) / 8, 256>>>(x);
    gbranch_kernel<<<B_, 256>>>(W1, W2);
    lconv_kernel<<<dim3(64, B_), 128>>>(Wl1);
    local_kernel<<<B_, 256>>>(Wl2);
    tam_main_kernel<<<(NBC * HW4_) / 256, 256>>>(x, out);
}

// round 3
// speedup vs baseline: 2.4211x; 1.1600x over previous
#include <cuda_runtime.h>
#include <math.h>

#define KSZ 7
#define PAD 3

#define B_  8
#define T_  16
#define C_  256
#define HW_ 784
#define HW4_ 196          // HW_/4 (float4)
#define NBC (B_ * C_)     // 2048
#define PSROW (T_ + 2 * PAD + 1)   // 23

// Scratch (no allocations allowed)
__device__ float d_pooled[B_ * C_ * T_];      // [b][c][t]
__device__ float d_Kern[B_ * C_ * KSZ];       // [b][c][k]
__device__ float d_Local[B_ * C_ * T_];       // [b][c][t]
__device__ float d_Y[B_ * 64 * T_];           // [b][o][t]

// ---------------------------------------------------------------------------
// Kernel 1: spatial mean pool. One warp per (b,t,c) row (784 contiguous f32).
// ---------------------------------------------------------------------------
__global__ void pool_kernel(const float* __restrict__ x) {
    const int warp = threadIdx.x >> 5;
    const int lane = threadIdx.x & 31;
    const int row  = blockIdx.x * 8 + warp;       // (b*T + t)*C + c
    const float4* xr = reinterpret_cast<const float4*>(x) + (size_t)row * HW4_;

    float s = 0.f;
    #pragma unroll 7
    for (int i = lane; i < HW4_; i += 32) {
        float4 v = xr[i];
        s += (v.x + v.y) + (v.z + v.w);
    }
    #pragma unroll
    for (int o = 16; o > 0; o >>= 1) s += __shfl_xor_sync(0xffffffffu, s, o);

    if (lane == 0) {
        int c  = row & (C_ - 1);
        int bt = row >> 8;
        int t  = bt & (T_ - 1);
        int b  = bt >> 4;
        d_pooled[(b * C_ + c) * T_ + t] = s * (1.0f / (float)HW_);
    }
}

// ---------------------------------------------------------------------------
// Kernel 2a: G branch. Grid = B_, 256 threads (thread = channel c).
// ---------------------------------------------------------------------------
__global__ void gbranch_kernel(const float* __restrict__ W1,   // [32][16]
                               const float* __restrict__ W2)   // [7][32]
{
    __shared__ float w1s[32 * 16];
    __shared__ float w2s[7 * 32];
    const int b = blockIdx.x;
    const int c = threadIdx.x;

    for (int i = c; i < 512; i += 256) w1s[i] = W1[i];
    if (c < 224) w2s[c] = W2[c];
    __syncthreads();

    float p[T_];
    const float4* pp = reinterpret_cast<const float4*>(d_pooled + (b * C_ + c) * T_);
    #pragma unroll
    for (int q = 0; q < 4; q++) {
        float4 v = pp[q];
        p[q * 4 + 0] = v.x; p[q * 4 + 1] = v.y; p[q * 4 + 2] = v.z; p[q * 4 + 3] = v.w;
    }

    float s[KSZ];
    #pragma unroll
    for (int k = 0; k < KSZ; k++) s[k] = 0.f;

    for (int u = 0; u < 32; u++) {
        float acc = 0.f;
        #pragma unroll
        for (int t = 0; t < T_; t++) acc += p[t] * w1s[u * 16 + t];
        float g = tanhf(acc);
        #pragma unroll
        for (int k = 0; k < KSZ; k++) s[k] += g * w2s[k * 32 + u];
    }
    float m = s[0];
    #pragma unroll
    for (int k = 1; k < KSZ; k++) m = fmaxf(m, s[k]);
    float e[KSZ], sum = 0.f;
    #pragma unroll
    for (int k = 0; k < KSZ; k++) { e[k] = expf(s[k] - m); sum += e[k]; }
    float inv = 1.0f / sum;
    #pragma unroll
    for (int k = 0; k < KSZ; k++)
        d_Kern[(b * C_ + c) * KSZ + k] = e[k] * inv;
}

// ---------------------------------------------------------------------------
// Kernel 2b: L-branch conv1d. Grid = (64 o, 8 b), 128 threads.
// ---------------------------------------------------------------------------
__global__ void lconv_kernel(const float* __restrict__ Wl1)    // [64][256][7]
{
    __shared__ float ps[C_ * PSROW];
    __shared__ float red[4][T_];

    const int o = blockIdx.x;
    const int b = blockIdx.y;
    const int tid  = threadIdx.x;
    const int lane = tid & 31;
    const int wrp  = tid >> 5;

    for (int i = tid; i < C_ * PSROW; i += 128) ps[i] = 0.f;
    __syncthreads();
    const float4* pp = reinterpret_cast<const float4*>(d_pooled + b * C_ * T_);
    for (int i = tid; i < C_ * T_ / 4; i += 128) {
        float4 v = pp[i];
        int e0 = i * 4;
        int c = e0 >> 4, t = e0 & 15;
        float* r = &ps[c * PSROW + PAD + t];
        r[0] = v.x; r[1] = v.y; r[2] = v.z; r[3] = v.w;
    }
    __syncthreads();

    float acc[T_];
    #pragma unroll
    for (int t = 0; t < T_; t++) acc[t] = 0.f;

    const float* w = Wl1 + o * (C_ * KSZ);
    #pragma unroll
    for (int ii = 0; ii < 2; ii++) {
        const int i = tid * 2 + ii;
        float wk[KSZ];
        #pragma unroll
        for (int k = 0; k < KSZ; k++) wk[k] = w[i * KSZ + k];
        float pv[T_ + 2 * PAD];
        #pragma unroll
        for (int j = 0; j < T_ + 2 * PAD; j++) pv[j] = ps[i * PSROW + j];
        #pragma unroll
        for (int t = 0; t < T_; t++) {
            #pragma unroll
            for (int k = 0; k < KSZ; k++)
                acc[t] += wk[k] * pv[t + k];
        }
    }

    #pragma unroll
    for (int off = 16; off > 0; off >>= 1) {
        #pragma unroll
        for (int t = 0; t < T_; t++)
            acc[t] += __shfl_xor_sync(0xffffffffu, acc[t], off);
    }
    if (lane == 0) {
        #pragma unroll
        for (int t = 0; t < T_; t++) red[wrp][t] = acc[t];
    }
    __syncthreads();
    if (tid < T_) {
        float s = red[0][tid] + red[1][tid] + red[2][tid] + red[3][tid];
        d_Y[(b * 64 + o) * T_ + tid] = tanhf(s);
    }
}

// ---------------------------------------------------------------------------
// Kernel 2c: local gate, re-gridded. One block per (b,t) = 128 blocks,
// 256 threads (thread = c). 16 independent float4 loads of the Wl2 row
// (L2-resident after first wave) + 64 FMAs vs broadcast ys tile.
// ---------------------------------------------------------------------------
__global__ void __launch_bounds__(256)
local_kernel(const float* __restrict__ Wl2)    // [256][64]
{
    __shared__ float ys[64];
    const int b = blockIdx.x >> 4;
    const int t = blockIdx.x & 15;
    const int c = threadIdx.x;

    if (c < 64) ys[c] = d_Y[(b * 64 + c) * T_ + t];
    __syncthreads();

    const float4* w = reinterpret_cast<const float4*>(Wl2) + c * 16;
    float acc = 0.f;
    #pragma unroll
    for (int q = 0; q < 16; q++) {
        float4 v = w[q];
        acc += v.x * ys[q * 4 + 0] + v.y * ys[q * 4 + 1]
             + v.z * ys[q * 4 + 2] + v.w * ys[q * 4 + 3];
    }
    d_Local[(b * C_ + c) * T_ + t] = 1.0f / (1.0f + expf(-acc));
}

// ---------------------------------------------------------------------------
// Kernel 3: main. Flat 256-thread blocks; one float4 lane per thread covering
// all 16 temporal slices (read x once, write once).
// ---------------------------------------------------------------------------
__global__ void __launch_bounds__(256)
tam_main_kernel(const float* __restrict__ x, float* __restrict__ out)
{
    const int g  = blockIdx.x * 256 + threadIdx.x;
    const int bc = g / HW4_;
    const int sp = g - bc * HW4_;
    const int b  = bc >> 8;
    const int c  = bc & (C_ - 1);

    float kr[KSZ];
    #pragma unroll
    for (int k = 0; k < KSZ; k++) kr[k] = d_Kern[bc * KSZ + k];
    float lr[T_];
    #pragma unroll
    for (int t = 0; t < T_; t++) lr[t] = d_Local[bc * T_ + t];

    const size_t base = (size_t)(b * T_ * C_ + c) * HW4_ + sp;
    const int tstride = C_ * HW4_;
    const float4* xp = reinterpret_cast<const float4*>(x) + base;
    float4*       op = reinterpret_cast<float4*>(out) + base;

    float4 gt[T_];
    #pragma unroll
    for (int t = 0; t < T_; t++) {
        float4 v = xp[t * tstride];
        float l = lr[t];
        gt[t].x = v.x * l; gt[t].y = v.y * l; gt[t].z = v.z * l; gt[t].w = v.w * l;
    }

    #pragma unroll
    for (int t = 0; t < T_; t++) {
        float4 a; a.x = a.y = a.z = a.w = 0.f;
        #pragma unroll
        for (int k = 0; k < KSZ; k++) {
            int ts = t + k - PAD;
            if (ts >= 0 && ts < T_) {
                float kk = kr[k];
                a.x += kk * gt[ts].x;
                a.y += kk * gt[ts].y;
                a.z += kk * gt[ts].z;
                a.w += kk * gt[ts].w;
            }
        }
        op[t * tstride] = a;
    }
}

// ---------------------------------------------------------------------------
extern "C" void kernel_launch(void* const* d_in, const int* in_sizes, int n_in,
                              void* d_out, int out_size) {
    const float* x   = (const float*)d_in[0];
    const float* W1  = (const float*)d_in[1];
    const float* W2  = (const float*)d_in[2];
    const float* Wl1 = (const float*)d_in[3];
    const float* Wl2 = (const float*)d_in[4];
    float* out = (float*)d_out;

    pool_kernel<<<(B_ * T_ * C_) / 8, 256>>>(x);
    gbranch_kernel<<<B_, 256>>>(W1, W2);
    lconv_kernel<<<dim3(64, B_), 128>>>(Wl1);
    local_kernel<<<B_ * T_, 256>>>(Wl2);
    tam_main_kernel<<<(NBC * HW4_) / 256, 256>>>(x, out);
}

// round 4
// speedup vs baseline: 2.4595x; 1.0159x over previous
#include <cuda_runtime.h>
#include <math.h>

#define KSZ 7
#define PAD 3

#define B_  8
#define T_  16
#define C_  256
#define HW_ 784
#define HW4_ 196          // HW_/4 (float4)
#define NBC (B_ * C_)     // 2048
#define PSROW (T_ + 2 * PAD + 1)   // 23

// Scratch (no allocations allowed)
__device__ float d_pooled[B_ * C_ * T_];      // [b][c][t]
__device__ float d_Kern[B_ * C_ * KSZ];       // [b][c][k]
__device__ float d_Yt[B_ * T_ * 64];          // [b][t][o]  (transposed for coalesced gate loads)

// ---------------------------------------------------------------------------
// Kernel 1: spatial mean pool. One warp per (b,t,c) row (784 contiguous f32).
// ---------------------------------------------------------------------------
__global__ void pool_kernel(const float* __restrict__ x) {
    const int warp = threadIdx.x >> 5;
    const int lane = threadIdx.x & 31;
    const int row  = blockIdx.x * 8 + warp;       // (b*T + t)*C + c
    const float4* xr = reinterpret_cast<const float4*>(x) + (size_t)row * HW4_;

    float s = 0.f;
    #pragma unroll 7
    for (int i = lane; i < HW4_; i += 32) {
        float4 v = xr[i];
        s += (v.x + v.y) + (v.z + v.w);
    }
    #pragma unroll
    for (int o = 16; o > 0; o >>= 1) s += __shfl_xor_sync(0xffffffffu, s, o);

    if (lane == 0) {
        int c  = row & (C_ - 1);
        int bt = row >> 8;
        int t  = bt & (T_ - 1);
        int b  = bt >> 4;
        d_pooled[(b * C_ + c) * T_ + t] = s * (1.0f / (float)HW_);
    }
}

// ---------------------------------------------------------------------------
// Kernel 2: fused coefficients. Grid = (65, 8), 128 threads.
//   blockIdx.x < 64 : conv1d output channel o for batch b  -> d_Yt[b][t][o]
//   blockIdx.x == 64: G branch for batch b (2 channels per thread) -> d_Kern
// ---------------------------------------------------------------------------
__global__ void coeff_kernel(const float* __restrict__ Wl1,   // [64][256][7]
                             const float* __restrict__ W1,    // [32][16]
                             const float* __restrict__ W2)    // [7][32]
{
    __shared__ float ps[C_ * PSROW];
    __shared__ float red[4][T_];
    __shared__ float w1s[32 * 16];
    __shared__ float w2s[7 * 32];

    const int b   = blockIdx.y;
    const int tid = threadIdx.x;          // 0..127

    if (blockIdx.x == 64) {
        // ---- G branch ----
        for (int i = tid; i < 512; i += 128) w1s[i] = W1[i];
        for (int i = tid; i < 224; i += 128) w2s[i] = W2[i];
        __syncthreads();

        #pragma unroll
        for (int cc = 0; cc < 2; cc++) {
            const int c = tid + cc * 128;
            float p[T_];
            const float4* pp = reinterpret_cast<const float4*>(d_pooled + (b * C_ + c) * T_);
            #pragma unroll
            for (int q = 0; q < 4; q++) {
                float4 v = pp[q];
                p[q*4+0]=v.x; p[q*4+1]=v.y; p[q*4+2]=v.z; p[q*4+3]=v.w;
            }
            float s[KSZ];
            #pragma unroll
            for (int k = 0; k < KSZ; k++) s[k] = 0.f;
            for (int u = 0; u < 32; u++) {
                float acc = 0.f;
                #pragma unroll
                for (int t = 0; t < T_; t++) acc += p[t] * w1s[u * 16 + t];
                float g = tanhf(acc);
                #pragma unroll
                for (int k = 0; k < KSZ; k++) s[k] += g * w2s[k * 32 + u];
            }
            float m = s[0];
            #pragma unroll
            for (int k = 1; k < KSZ; k++) m = fmaxf(m, s[k]);
            float e[KSZ], sum = 0.f;
            #pragma unroll
            for (int k = 0; k < KSZ; k++) { e[k] = expf(s[k] - m); sum += e[k]; }
            float inv = 1.0f / sum;
            #pragma unroll
            for (int k = 0; k < KSZ; k++)
                d_Kern[(b * C_ + c) * KSZ + k] = e[k] * inv;
        }
        return;
    }

    // ---- L-branch conv1d: output channel o = blockIdx.x ----
    const int o = blockIdx.x;
    const int lane = tid & 31;
    const int wrp  = tid >> 5;

    for (int i = tid; i < C_ * PSROW; i += 128) ps[i] = 0.f;
    __syncthreads();
    const float4* pp = reinterpret_cast<const float4*>(d_pooled + b * C_ * T_);
    for (int i = tid; i < C_ * T_ / 4; i += 128) {
        float4 v = pp[i];
        int e0 = i * 4;
        int c = e0 >> 4, t = e0 & 15;
        float* r = &ps[c * PSROW + PAD + t];
        r[0] = v.x; r[1] = v.y; r[2] = v.z; r[3] = v.w;
    }
    __syncthreads();

    float acc[T_];
    #pragma unroll
    for (int t = 0; t < T_; t++) acc[t] = 0.f;

    const float* w = Wl1 + o * (C_ * KSZ);
    #pragma unroll
    for (int ii = 0; ii < 2; ii++) {
        const int i = tid * 2 + ii;
        float wk[KSZ];
        #pragma unroll
        for (int k = 0; k < KSZ; k++) wk[k] = w[i * KSZ + k];
        float pv[T_ + 2 * PAD];
        #pragma unroll
        for (int j = 0; j < T_ + 2 * PAD; j++) pv[j] = ps[i * PSROW + j];
        #pragma unroll
        for (int t = 0; t < T_; t++) {
            #pragma unroll
            for (int k = 0; k < KSZ; k++)
                acc[t] += wk[k] * pv[t + k];
        }
    }

    #pragma unroll
    for (int off = 16; off > 0; off >>= 1) {
        #pragma unroll
        for (int t = 0; t < T_; t++)
            acc[t] += __shfl_xor_sync(0xffffffffu, acc[t], off);
    }
    if (lane == 0) {
        #pragma unroll
        for (int t = 0; t < T_; t++) red[wrp][t] = acc[t];
    }
    __syncthreads();
    if (tid < T_) {
        float s = red[0][tid] + red[1][tid] + red[2][tid] + red[3][tid];
        d_Yt[(b * T_ + tid) * 64 + o] = tanhf(s);   // transposed store
    }
}

// ---------------------------------------------------------------------------
// Kernel 3: main. One block per (b,c), 196 threads (one float4 lane each).
//   Prologue: threads 0..15 compute the 16 sigmoid gates (Wl2 . Yt) in smem.
//   Body: sliding-window over t — load slice s, emit out[s-3]; live window of
//   7 float4 regs; streaming stores (__stcs) keep x resident in L2.
// ---------------------------------------------------------------------------
__global__ void __launch_bounds__(196)
tam_main_kernel(const float* __restrict__ x, float* __restrict__ out,
                const float* __restrict__ Wl2)   // [256][64]
{
    __shared__ float lrs[T_];
    const int bc  = blockIdx.x;
    const int b   = bc >> 8;
    const int c   = bc & (C_ - 1);
    const int tid = threadIdx.x;     // 0..195

    // per-(b,c) gate row (redundant per block, ~1K FLOP -> free)
    if (tid < T_) {
        const float4* wv = reinterpret_cast<const float4*>(Wl2 + c * 64);
        const float4* yv = reinterpret_cast<const float4*>(d_Yt + (b * T_ + tid) * 64);
        float acc = 0.f;
        #pragma unroll
        for (int q = 0; q < 16; q++) {
            float4 wq = wv[q], yq = yv[q];
            acc += wq.x * yq.x + wq.y * yq.y + wq.z * yq.z + wq.w * yq.w;
        }
        lrs[tid] = 1.0f / (1.0f + expf(-acc));
    }

    float kr[KSZ];
    #pragma unroll
    for (int k = 0; k < KSZ; k++) kr[k] = d_Kern[bc * KSZ + k];

    __syncthreads();
    float lr[T_];
    #pragma unroll
    for (int t = 0; t < T_; t++) lr[t] = lrs[t];

    const size_t base = (size_t)(b * T_ * C_ + c) * HW4_ + tid;   // t=0 slice
    const int tstride = C_ * HW4_;
    const float4* xp = reinterpret_cast<const float4*>(x) + base;
    float4*       op = reinterpret_cast<float4*>(out) + base;

    float4 g[T_];
    #pragma unroll
    for (int s = 0; s < T_ + PAD; s++) {
        if (s < T_) {
            float4 v = xp[s * tstride];
            float l = lr[s];
            g[s].x = v.x * l; g[s].y = v.y * l; g[s].z = v.z * l; g[s].w = v.w * l;
        }
        if (s >= PAD) {
            const int t = s - PAD;
            float4 a; a.x = a.y = a.z = a.w = 0.f;
            #pragma unroll
            for (int k = 0; k < KSZ; k++) {
                int u = t + k - PAD;
                if (u >= 0 && u < T_) {          // constant-folded; u <= s always
                    float kk = kr[k];
                    a.x += kk * g[u].x;
                    a.y += kk * g[u].y;
                    a.z += kk * g[u].z;
                    a.w += kk * g[u].w;
                }
            }
            __stcs(op + t * tstride, a);          // streaming: don't pollute L2
        }
    }
}

// ---------------------------------------------------------------------------
extern "C" void kernel_launch(void* const* d_in, const int* in_sizes, int n_in,
                              void* d_out, int out_size) {
    const float* x   = (const float*)d_in[0];
    const float* W1  = (const float*)d_in[1];
    const float* W2  = (const float*)d_in[2];
    const float* Wl1 = (const float*)d_in[3];
    const float* Wl2 = (const float*)d_in[4];
    float* out = (float*)d_out;

    pool_kernel<<<(B_ * T_ * C_) / 8, 256>>>(x);
    coeff_kernel<<<dim3(65, B_), 128>>>(Wl1, W1, W2);
    tam_main_kernel<<<NBC, 196>>>(x, out, Wl2);
}